// round 13
// baseline (speedup 1.0000x reference)
#include <cuda_runtime.h>
#include <cuda_fp16.h>
#include <math.h>

// Problem constants
#define B_SZ   64
#define BG     32            // batch-group size
#define NGROUP 2
#define I_CAPS 2048
#define D_DIM  16
#define JK     512
#define NI     8             // i's per k_uhat2 block
#define NCHUNK_U (I_CAPS / NI)   // 256: partial chunks produced by k_uhat2
#define NCHUNK_P 32              // partial chunks produced by k_pass (64 i/CTA)

// Scratch (device globals — allocation-free rule)
__device__ __half g_uhat[(size_t)BG * I_CAPS * JK];       // 67 MB group slice
__device__ float  g_part[NCHUNK_U * BG * JK];             // 16.7 MB partials
__device__ float  g_out1[B_SZ * JK];
__device__ float  g_outc[B_SZ * JK];

// ---- packed f32x2 helpers (FFMA2/FADD2 only reachable via PTX) -------------
__device__ __forceinline__ void fma2(unsigned long long& d,
                                     unsigned long long a, unsigned long long b) {
    asm("fma.rn.f32x2 %0, %1, %2, %0;" : "+l"(d) : "l"(a), "l"(b));
}
__device__ __forceinline__ void add2(unsigned long long& d, unsigned long long a) {
    asm("add.rn.f32x2 %0, %0, %1;" : "+l"(d) : "l"(a));
}
__device__ __forceinline__ float2 up2(unsigned long long v) {
    float2 r;
    asm("mov.b64 {%0,%1}, %2;" : "=f"(r.x), "=f"(r.y) : "l"(v));
    return r;
}

// ---- warp allreduce-add (redux.f32 unsupported on sm_103) -------------------
__device__ __forceinline__ float warp_sum(float v) {
    v += __shfl_xor_sync(0xffffffffu, v, 1);
    v += __shfl_xor_sync(0xffffffffu, v, 2);
    v += __shfl_xor_sync(0xffffffffu, v, 4);
    v += __shfl_xor_sync(0xffffffffu, v, 8);
    v += __shfl_xor_sync(0xffffffffu, v, 16);
    return v;
}

// ---- 32B loads (.v4.b64 — the form this ptxas accepts with L2 hints) -------
struct U8 { uint4 a, b; };

__device__ __forceinline__ U8 ldg_v8(const void* p) {
    U8 v;
    asm("ld.global.v4.b64 {%0,%1,%2,%3}, [%4];"
        : "=l"(*(unsigned long long*)&v.a.x),
          "=l"(*(unsigned long long*)&v.a.z),
          "=l"(*(unsigned long long*)&v.b.x),
          "=l"(*(unsigned long long*)&v.b.z) : "l"(p));
    return v;
}
__device__ __forceinline__ U8 ldg_v8_ef(const void* p) {          // dead data
    U8 v;
    asm("ld.global.L2::evict_first.v4.b64 {%0,%1,%2,%3}, [%4];"
        : "=l"(*(unsigned long long*)&v.a.x),
          "=l"(*(unsigned long long*)&v.a.z),
          "=l"(*(unsigned long long*)&v.b.x),
          "=l"(*(unsigned long long*)&v.b.z) : "l"(p));
    return v;
}
__device__ __forceinline__ U8 ldg_v8_stream(const void* p) {      // W: stream once
    U8 v;
    asm("ld.global.nc.L2::evict_first.v4.b64 {%0,%1,%2,%3}, [%4];"
        : "=l"(*(unsigned long long*)&v.a.x),
          "=l"(*(unsigned long long*)&v.a.z),
          "=l"(*(unsigned long long*)&v.b.x),
          "=l"(*(unsigned long long*)&v.b.z) : "l"(p));
    return v;
}

// ---------------------------------------------------------------------------
// K1 fused with round-1 reduction. Block = 8 consecutive i x 16 lb.
// 256 threads; thread t owns jk columns {2t, 2t+1}: j = t>>3, k0 = (t&7)*2.
// (Round-12 bug: 4-col mapping with 256 threads -> j up to 63 -> OOB. Fixed.)
// W[i] staged through smem per i-stage; x pre-duplicated (v,v).
// Per (i,lb): u stored fp16 to g_uhat AND accumulated in fp32 (pre-rounding)
// into register partials -> g_part. Eliminates the pass<0> read sweep.
// ---------------------------------------------------------------------------
__global__ void __launch_bounds__(256, 2)
k_uhat2(const float* __restrict__ x, const float* __restrict__ W, int b_base) {
    __shared__ float  Wsh[8192];                 // 32 KB, re-staged per i
    __shared__ float2 xdup[NI][16][D_DIM];       // 16 KB

    const int i_base  = blockIdx.x * NI;
    const int lb_base = blockIdx.y * 16;
    const int t = threadIdx.x;

    // Stage x for 8 i x 16 lb x 16 d (pre-duplicated pairs): 2048 entries
    #pragma unroll
    for (int r = 0; r < 8; r++) {
        const int e  = t + 256 * r;
        const int il = e >> 8;
        const int rem = e & 255;
        const int lb = rem >> 4, d = rem & 15;
        const float v = x[((size_t)(b_base + lb_base + lb) * I_CAPS
                          + i_base + il) * D_DIM + d];
        xdup[il][lb][d] = make_float2(v, v);
    }

    const int j  = t >> 3;             // 0..31
    const int k0 = (t & 7) * 2;        // 0..14 (even)

    unsigned long long acc[16];                  // per-lb fp32x2 partial sums
    #pragma unroll
    for (int lb = 0; lb < 16; lb++) acc[lb] = 0ull;

    for (int s = 0; s < NI; s++) {
        const int i = i_base + s;
        __syncthreads();                         // prior stage's smem reads done
        {
            const char* Wg = reinterpret_cast<const char*>(W + (size_t)i * 8192);
            U8* Ws8 = reinterpret_cast<U8*>(Wsh);
            #pragma unroll
            for (int r = 0; r < 4; r++)
                Ws8[t + 256 * r] = ldg_v8_stream(Wg + 32 * (t + 256 * r));
        }
        __syncthreads();

        unsigned long long wA[D_DIM];
        #pragma unroll
        for (int d = 0; d < D_DIM; d++)
            wA[d] = *reinterpret_cast<const unsigned long long*>(
                        &Wsh[j * 256 + d * 16 + k0]);

        __half* outp = g_uhat + (size_t)i * JK + 2 * t;
        #pragma unroll 2
        for (int lb = 0; lb < 16; lb++) {
            unsigned long long u01 = 0ull;
            #pragma unroll
            for (int d = 0; d < D_DIM; d++) {
                const unsigned long long xx =
                    *reinterpret_cast<const unsigned long long*>(&xdup[s][lb][d]);
                fma2(u01, xx, wA[d]);
            }
            add2(acc[lb], u01);                  // round-1 partial (fp32)
            const float2 a = up2(u01);
            __half2 h0 = __float22half2_rn(make_float2(a.x, a.y));
            *reinterpret_cast<unsigned int*>(
                outp + (size_t)(lb_base + lb) * ((size_t)I_CAPS * JK)) =
                *reinterpret_cast<unsigned int*>(&h0);
        }
    }

    // Round-1 partials: [chunk][lb][jk], coalesced float2 per lb
    float* pp = g_part + ((size_t)blockIdx.x * BG + lb_base) * JK + 2 * t;
    #pragma unroll
    for (int lb = 0; lb < 16; lb++) {
        const float2 a = up2(acc[lb]);
        *reinterpret_cast<float2*>(pp + (size_t)lb * JK) = a;
    }
}

// ---------------------------------------------------------------------------
// Routing pass (rounds 2 & 3). blockIdx.y = lb, blockIdx.x = chunk of 64 i.
// 4 warps x 16 i. Lane l owns j=l, all k=16: ONE 32B LDG per i.
// KEEP=0 (final pass): evict_first to free L2 for the next group.
// Lane-local logit dot; softmax over j = 5-shuffle z-allreduce.
// ---------------------------------------------------------------------------
template <int KEEP>
__global__ void __launch_bounds__(128, 8)
k_pass(int which_out, int b_base) {
    __shared__ float red[4][16 * 33];

    const int lb = blockIdx.y;
    const int t = threadIdx.x;
    const int w = t >> 5;
    const int l = t & 31;

    float o[16];
    {
        const float* outv = (which_out == 0) ? g_out1 : g_outc;
        const float4* op = reinterpret_cast<const float4*>(
            outv + (size_t)(b_base + lb) * JK + l * 16);
        #pragma unroll
        for (int q = 0; q < 4; q++) {
            float4 v = op[q];
            o[q * 4] = v.x; o[q * 4 + 1] = v.y; o[q * 4 + 2] = v.z; o[q * 4 + 3] = v.w;
        }
    }

    float acc[16];
    #pragma unroll
    for (int m = 0; m < 16; m++) acc[m] = 0.f;

    const __half* base = g_uhat + ((size_t)lb * I_CAPS
                       + (size_t)(blockIdx.x * 64 + w * 16)) * JK;
    const char* p = reinterpret_cast<const char*>(base) + 32 * l;

    #pragma unroll
    for (int ii = 0; ii < 16; ii++) {
        const U8 r8 = KEEP ? ldg_v8(p + ii * 1024) : ldg_v8_ef(p + ii * 1024);

        float u[16];
        {
            const unsigned int* pa = &r8.a.x;
            const unsigned int* pb = &r8.b.x;
            #pragma unroll
            for (int h = 0; h < 4; h++) {
                float2 va = __half22float2(*reinterpret_cast<const __half2*>(&pa[h]));
                u[h * 2] = va.x; u[h * 2 + 1] = va.y;
                float2 vb = __half22float2(*reinterpret_cast<const __half2*>(&pb[h]));
                u[8 + h * 2] = vb.x; u[8 + h * 2 + 1] = vb.y;
            }
        }

        float lg = 0.f;
        #pragma unroll
        for (int m = 0; m < 16; m++) lg = fmaf(u[m], o[m], lg);
        const float e = __expf(lg);
        const float z = warp_sum(e);
        const float c = __fdividef(e, z);
        #pragma unroll
        for (int m = 0; m < 16; m++) acc[m] = fmaf(c, u[m], acc[m]);
    }

    #pragma unroll
    for (int m = 0; m < 16; m++) red[w][m * 33 + l] = acc[m];
    __syncthreads();

    const int lo = t >> 2;
    const int mo = (t & 3) * 4;
    float4 s;
    float* sp = &s.x;
    #pragma unroll
    for (int c = 0; c < 4; c++) {
        float v = 0.f;
        #pragma unroll
        for (int w2 = 0; w2 < 4; w2++) v += red[w2][(mo + c) * 33 + lo];
        sp[c] = v;
    }
    *reinterpret_cast<float4*>(
        &g_part[((size_t)blockIdx.x * BG + lb) * JK + 4 * t]) = s;
}

// ---------------------------------------------------------------------------
// Squash (per group): reduce NC chunk-partials, squash per (b,j) over k=16.
// mode 0 -> g_out1 ; mode 1 -> g_outc = g_out1 + squash ; mode 2 -> d_out.
// ---------------------------------------------------------------------------
template <int NC>
__global__ void __launch_bounds__(512)
k_squash(int mode, float* __restrict__ dout, int b_base) {
    const int lb = blockIdx.x;
    const int t = threadIdx.x;
    const int b = b_base + lb;

    float v = 0.f;
    #pragma unroll 8
    for (int c = 0; c < NC; c++) v += g_part[((size_t)c * BG + lb) * JK + t];
    if (mode == 0) v *= (1.f / 32.f);

    float sq = v * v;
    sq += __shfl_xor_sync(0xffffffffu, sq, 1);
    sq += __shfl_xor_sync(0xffffffffu, sq, 2);
    sq += __shfl_xor_sync(0xffffffffu, sq, 4);
    sq += __shfl_xor_sync(0xffffffffu, sq, 8);

    const float scale = sq / ((1.f + sq) * sqrtf(sq + 1e-7f));
    const float o = scale * v;

    if (mode == 0)      g_out1[(size_t)b * JK + t] = o;
    else if (mode == 1) g_outc[(size_t)b * JK + t] = g_out1[(size_t)b * JK + t] + o;
    else                dout[(size_t)b * JK + t] = o;
}

// ---------------------------------------------------------------------------
extern "C" void kernel_launch(void* const* d_in, const int* in_sizes, int n_in,
                              void* d_out, int out_size) {
    const float* x = (const float*)d_in[0];
    const float* W = (const float*)d_in[1];
    if (n_in >= 2 && in_sizes[0] == 16777216 && in_sizes[1] == 2097152) {
        const float* tmp = x; x = W; W = tmp;
    }
    float* out = (float*)d_out;

    for (int g = 0; g < NGROUP; g++) {
        const int b0 = g * BG;

        // Fused u_hat + round-1 partial sums (no pass<0> sweep)
        dim3 ug(NCHUNK_U, 2);
        k_uhat2<<<ug, 256>>>(x, W, b0);
        k_squash<NCHUNK_U><<<BG, 512>>>(0, nullptr, b0);

        dim3 pg(NCHUNK_P, BG);
        k_pass<1><<<pg, 128>>>(0, b0);           // round 2
        k_squash<NCHUNK_P><<<BG, 512>>>(1, nullptr, b0);
        k_pass<0><<<pg, 128>>>(1, b0);           // round 3 (release L2)
        k_squash<NCHUNK_P><<<BG, 512>>>(2, out, b0);
    }
}

// round 14
// speedup vs baseline: 1.2685x; 1.2685x over previous
#include <cuda_runtime.h>
#include <cuda_fp16.h>
#include <math.h>

// Problem constants
#define B_SZ   64
#define BG     32            // batch-group size
#define NGROUP 2
#define I_CAPS 2048
#define D_DIM  16
#define JK     512
#define IPC    64            // i per pass-CTA
#define SI     8             // i per pipeline stage (8 KB)
#define NITER  (IPC / SI)    // 8 stages
#define NSTAGE 3             // smem buffers
#define NCHUNK 32            // pass chunks (2048/64)

// Scratch (device globals — allocation-free rule)
__device__ __half g_uhat[(size_t)BG * I_CAPS * JK];       // 67 MB group slice
__device__ float  g_part[NCHUNK * BG * JK];               // 2 MB partials
__device__ float  g_out1[B_SZ * JK];
__device__ float  g_outc[B_SZ * JK];

// ---- packed f32x2 helpers (FFMA2 only reachable via PTX) ------------------
__device__ __forceinline__ void fma2(unsigned long long& d,
                                     unsigned long long a, unsigned long long b) {
    asm("fma.rn.f32x2 %0, %1, %2, %0;" : "+l"(d) : "l"(a), "l"(b));
}
__device__ __forceinline__ float2 up2(unsigned long long v) {
    float2 r;
    asm("mov.b64 {%0,%1}, %2;" : "=f"(r.x), "=f"(r.y) : "l"(v));
    return r;
}

// ---- warp allreduce-add (redux.f32 unsupported on sm_103) ------------------
__device__ __forceinline__ float warp_sum(float v) {
    v += __shfl_xor_sync(0xffffffffu, v, 1);
    v += __shfl_xor_sync(0xffffffffu, v, 2);
    v += __shfl_xor_sync(0xffffffffu, v, 4);
    v += __shfl_xor_sync(0xffffffffu, v, 8);
    v += __shfl_xor_sync(0xffffffffu, v, 16);
    return v;
}

// ---- 32B streaming load for W (nc + evict_first, .v4.b64 form) -------------
struct U8 { uint4 a, b; };
__device__ __forceinline__ U8 ldg_v8_stream(const void* p) {
    U8 v;
    asm("ld.global.nc.L2::evict_first.v4.b64 {%0,%1,%2,%3}, [%4];"
        : "=l"(*(unsigned long long*)&v.a.x),
          "=l"(*(unsigned long long*)&v.a.z),
          "=l"(*(unsigned long long*)&v.b.x),
          "=l"(*(unsigned long long*)&v.b.z) : "l"(p));
    return v;
}

// ---- cp.async primitives ----------------------------------------------------
__device__ __forceinline__ void cpa16(unsigned int dst, const void* src) {
    asm volatile("cp.async.cg.shared.global [%0], [%1], 16;"
                 :: "r"(dst), "l"(src));
}
#define CP_COMMIT()  asm volatile("cp.async.commit_group;")
#define CP_WAIT1()   asm volatile("cp.async.wait_group 1;")

// ---------------------------------------------------------------------------
// K1 (per group, round-9 proven): u_hat[lb,i,jk] = x[b0+lb,i,:] @ W[i], fp16.
// One block (128 thr) per i. W[i] in smem, reused across 32 lb; x (v,v)-dup.
// ---------------------------------------------------------------------------
__global__ void __launch_bounds__(128)
k_uhat(const float* __restrict__ x, const float* __restrict__ W, int b_base) {
    __shared__ float  Wsh[8192];
    __shared__ float2 xdup[BG][D_DIM];

    const int i = blockIdx.x;
    const int t = threadIdx.x;

    {
        const char* Wg = reinterpret_cast<const char*>(W + (size_t)i * 8192);
        U8* Ws8 = reinterpret_cast<U8*>(Wsh);
        #pragma unroll
        for (int r = 0; r < 8; r++)
            Ws8[t + 128 * r] = ldg_v8_stream(Wg + 32 * (t + 128 * r));
    }
    {
        #pragma unroll
        for (int r = 0; r < 4; r++) {
            const int e = t + 128 * r;
            const int lb = e >> 4, d = e & 15;
            const float v = x[((size_t)(b_base + lb) * I_CAPS + i) * D_DIM + d];
            xdup[lb][d] = make_float2(v, v);
        }
    }
    __syncthreads();

    const int j  = t >> 2;
    const int k0 = (t & 3) * 4;

    unsigned long long wA[D_DIM], wB[D_DIM];
    #pragma unroll
    for (int d = 0; d < D_DIM; d++) {
        const float* wp = &Wsh[j * 256 + d * 16 + k0];
        wA[d] = *reinterpret_cast<const unsigned long long*>(wp);
        wB[d] = *reinterpret_cast<const unsigned long long*>(wp + 2);
    }

    __half* outp = g_uhat + (size_t)i * JK + 4 * t;
    #pragma unroll 2
    for (int lb = 0; lb < BG; lb++) {
        unsigned long long u01 = 0ull, u23 = 0ull;
        #pragma unroll
        for (int d = 0; d < D_DIM; d++) {
            const unsigned long long xx =
                *reinterpret_cast<const unsigned long long*>(&xdup[lb][d]);
            fma2(u01, xx, wA[d]);
            fma2(u23, xx, wB[d]);
        }
        const float2 a = up2(u01), c = up2(u23);
        __half2 h0 = __float22half2_rn(make_float2(a.x, a.y));
        __half2 h1 = __float22half2_rn(make_float2(c.x, c.y));
        uint2 st;
        st.x = *reinterpret_cast<unsigned int*>(&h0);
        st.y = *reinterpret_cast<unsigned int*>(&h1);
        *reinterpret_cast<uint2*>(outp + (size_t)lb * ((size_t)I_CAPS * JK)) = st;
    }
}

// ---------------------------------------------------------------------------
// Routing pass with cp.async pipeline. blockIdx.y = lb, blockIdx.x = chunk of
// 64 i (contiguous 64 KB region). 3-stage x 8 KB smem pipeline, prefetch 2.
// Stage store layout deinterleaves 16B chunks per 1KB row: even chunk c -> byte
// (c/2)*16, odd -> 512+(c/2)*16, so lane l's two 16B reads (j=l, k 0..7 / 8..15)
// are lane-stride-16B LDS.128 -> conflict-free.
// Warp w processes i_local = s*8 + w*2 + {0,1} per stage.
// MODE 1: lane-local logit dot; softmax over j = 5-shuffle z-allreduce.
// Reduction buffer aliased into the pipeline smem after the loop.
// ---------------------------------------------------------------------------
template <int MODE>
__global__ void __launch_bounds__(128, 8)
k_pass(int which_out, int b_base) {
    __shared__ __align__(16) char smemraw[NSTAGE * 8192];   // 24 KB

    const int lb = blockIdx.y;
    const int t = threadIdx.x;
    const int w = t >> 5;
    const int l = t & 31;

    const char* region = reinterpret_cast<const char*>(
        g_uhat + ((size_t)lb * I_CAPS + (size_t)blockIdx.x * IPC) * JK);
    const unsigned int sb =
        (unsigned int)__cvta_generic_to_shared(smemraw);

    float o[16];
    if (MODE == 1) {
        const float* outv = (which_out == 0) ? g_out1 : g_outc;
        const float4* op = reinterpret_cast<const float4*>(
            outv + (size_t)(b_base + lb) * JK + l * 16);
        #pragma unroll
        for (int q = 0; q < 4; q++) {
            float4 v = op[q];
            o[q * 4] = v.x; o[q * 4 + 1] = v.y; o[q * 4 + 2] = v.z; o[q * 4 + 3] = v.w;
        }
    }

    float acc[16];
    #pragma unroll
    for (int m = 0; m < 16; m++) acc[m] = 0.f;

    // --- stage loader: 4 x 16B per thread, deinterleaved dst ---
    auto load_stage = [&](int s) {
        const unsigned int dbase = sb + (unsigned int)((s % NSTAGE) * 8192);
        const char* gsrc = region + (size_t)s * 8192;
        #pragma unroll
        for (int r = 0; r < 4; r++) {
            const int e = t + 128 * r;            // 0..511
            const int row = e >> 6;               // 0..7
            const int c = e & 63;
            const unsigned int dst =
                dbase + (unsigned int)(row * 1024 + ((c & 1) << 9) + ((c >> 1) << 4));
            cpa16(dst, gsrc + (size_t)e * 16);
        }
    };

    load_stage(0); CP_COMMIT();
    load_stage(1); CP_COMMIT();

    for (int s = 0; s < NITER; s++) {
        CP_WAIT1();              // stage s complete (<=1 group pending)
        __syncthreads();         // visible to all; prior stage fully processed
        if (s + 2 < NITER) load_stage(s + 2);
        CP_COMMIT();             // commit (possibly empty) keeps group count aligned

        const char* st = smemraw + (s % NSTAGE) * 8192;
        #pragma unroll
        for (int q = 0; q < 2; q++) {
            const int row = w * 2 + q;
            const uint4 A = *reinterpret_cast<const uint4*>(st + row * 1024 + l * 16);
            const uint4 B = *reinterpret_cast<const uint4*>(st + row * 1024 + 512 + l * 16);

            float u[16];
            {
                const unsigned int* pa = &A.x;
                const unsigned int* pb = &B.x;
                #pragma unroll
                for (int h = 0; h < 4; h++) {
                    float2 va = __half22float2(*reinterpret_cast<const __half2*>(&pa[h]));
                    u[h * 2] = va.x; u[h * 2 + 1] = va.y;
                    float2 vb = __half22float2(*reinterpret_cast<const __half2*>(&pb[h]));
                    u[8 + h * 2] = vb.x; u[8 + h * 2 + 1] = vb.y;
                }
            }

            if (MODE == 1) {
                float lg = 0.f;
                #pragma unroll
                for (int m = 0; m < 16; m++) lg = fmaf(u[m], o[m], lg);
                const float e = __expf(lg);
                const float z = warp_sum(e);
                const float c = __fdividef(e, z);
                #pragma unroll
                for (int m = 0; m < 16; m++) acc[m] = fmaf(c, u[m], acc[m]);
            } else {
                #pragma unroll
                for (int m = 0; m < 16; m++) acc[m] += u[m];
            }
        }
    }

    // --- cross-warp reduction: alias red into the (now dead) pipeline smem ---
    __syncthreads();
    float* red = reinterpret_cast<float*>(smemraw);    // [4][16*33] = 8448 B
    #pragma unroll
    for (int m = 0; m < 16; m++) red[w * 528 + m * 33 + l] = acc[m];
    __syncthreads();

    const int lo = t >> 2;
    const int mo = (t & 3) * 4;
    float4 s4;
    float* sp = &s4.x;
    #pragma unroll
    for (int c = 0; c < 4; c++) {
        float v = 0.f;
        #pragma unroll
        for (int w2 = 0; w2 < 4; w2++) v += red[w2 * 528 + (mo + c) * 33 + lo];
        sp[c] = v;
    }
    *reinterpret_cast<float4*>(
        &g_part[((size_t)blockIdx.x * BG + lb) * JK + 4 * t]) = s4;
}

// ---------------------------------------------------------------------------
// Squash (per group): reduce 32 chunk-partials, squash per (b,j) over k=16.
// mode 0 -> g_out1 ; mode 1 -> g_outc = g_out1 + squash ; mode 2 -> d_out.
// ---------------------------------------------------------------------------
__global__ void __launch_bounds__(512)
k_squash(int mode, float* __restrict__ dout, int b_base) {
    const int lb = blockIdx.x;
    const int t = threadIdx.x;
    const int b = b_base + lb;

    float v = 0.f;
    #pragma unroll
    for (int c = 0; c < NCHUNK; c++) v += g_part[((size_t)c * BG + lb) * JK + t];
    if (mode == 0) v *= (1.f / 32.f);

    float sq = v * v;
    sq += __shfl_xor_sync(0xffffffffu, sq, 1);
    sq += __shfl_xor_sync(0xffffffffu, sq, 2);
    sq += __shfl_xor_sync(0xffffffffu, sq, 4);
    sq += __shfl_xor_sync(0xffffffffu, sq, 8);

    const float scale = sq / ((1.f + sq) * sqrtf(sq + 1e-7f));
    const float out = scale * v;

    if (mode == 0)      g_out1[(size_t)b * JK + t] = out;
    else if (mode == 1) g_outc[(size_t)b * JK + t] = g_out1[(size_t)b * JK + t] + out;
    else                dout[(size_t)b * JK + t] = out;
}

// ---------------------------------------------------------------------------
extern "C" void kernel_launch(void* const* d_in, const int* in_sizes, int n_in,
                              void* d_out, int out_size) {
    const float* x = (const float*)d_in[0];
    const float* W = (const float*)d_in[1];
    if (n_in >= 2 && in_sizes[0] == 16777216 && in_sizes[1] == 2097152) {
        const float* tmp = x; x = W; W = tmp;
    }
    float* out = (float*)d_out;

    for (int g = 0; g < NGROUP; g++) {
        const int b0 = g * BG;
        k_uhat<<<I_CAPS, 128>>>(x, W, b0);

        dim3 pg(NCHUNK, BG);
        k_pass<0><<<pg, 128>>>(0, b0);           // round 1
        k_squash<<<BG, 512>>>(0, nullptr, b0);
        k_pass<1><<<pg, 128>>>(0, b0);           // round 2
        k_squash<<<BG, 512>>>(1, nullptr, b0);
        k_pass<1><<<pg, 128>>>(1, b0);           // round 3
        k_squash<<<BG, 512>>>(2, out, b0);
    }
}

// round 15
// speedup vs baseline: 1.5267x; 1.2036x over previous
#include <cuda_runtime.h>
#include <cuda_fp16.h>
#include <math.h>

// Problem constants
#define B_SZ   64
#define BG     32            // batch-group size for k_uhat (W L2-reuse)
#define NGROUP 2
#define I_CAPS 2048
#define D_DIM  16
#define JK     512
#define NCHUNK 32            // pass chunks (64 i per CTA)

// Scratch (device globals — allocation-free rule)
__device__ __half g_uhat[(size_t)B_SZ * I_CAPS * JK];     // 134 MB, [b][i][jk]
__device__ float  g_part[NCHUNK * B_SZ * JK];             // 4 MB partials
__device__ float  g_out1[B_SZ * JK];
__device__ float  g_outc[B_SZ * JK];

// ---- packed f32x2 helpers (FFMA2 only reachable via PTX) ------------------
__device__ __forceinline__ void fma2(unsigned long long& d,
                                     unsigned long long a, unsigned long long b) {
    asm("fma.rn.f32x2 %0, %1, %2, %0;" : "+l"(d) : "l"(a), "l"(b));
}
__device__ __forceinline__ float2 up2(unsigned long long v) {
    float2 r;
    asm("mov.b64 {%0,%1}, %2;" : "=f"(r.x), "=f"(r.y) : "l"(v));
    return r;
}

// ---- warp allreduce-add (redux.f32 unsupported on sm_103) ------------------
__device__ __forceinline__ float warp_sum(float v) {
    v += __shfl_xor_sync(0xffffffffu, v, 1);
    v += __shfl_xor_sync(0xffffffffu, v, 2);
    v += __shfl_xor_sync(0xffffffffu, v, 4);
    v += __shfl_xor_sync(0xffffffffu, v, 8);
    v += __shfl_xor_sync(0xffffffffu, v, 16);
    return v;
}

// ---- 32B loads (.v4.b64) ----------------------------------------------------
struct U8 { uint4 a, b; };

__device__ __forceinline__ U8 ldg_v8(const void* p) {
    U8 v;
    asm("ld.global.v4.b64 {%0,%1,%2,%3}, [%4];"
        : "=l"(*(unsigned long long*)&v.a.x),
          "=l"(*(unsigned long long*)&v.a.z),
          "=l"(*(unsigned long long*)&v.b.x),
          "=l"(*(unsigned long long*)&v.b.z) : "l"(p));
    return v;
}
__device__ __forceinline__ U8 ldg_v8_stream(const void* p) {      // W: stream
    U8 v;
    asm("ld.global.nc.L2::evict_first.v4.b64 {%0,%1,%2,%3}, [%4];"
        : "=l"(*(unsigned long long*)&v.a.x),
          "=l"(*(unsigned long long*)&v.a.z),
          "=l"(*(unsigned long long*)&v.b.x),
          "=l"(*(unsigned long long*)&v.b.z) : "l"(p));
    return v;
}

// ---------------------------------------------------------------------------
// K1 (grouped, round-9 proven schedule): u_hat[b0+lb,i,jk] = x @ W[i], fp16.
// One block (128 thr) per i; W[i] in smem reused across 32 lb; x (v,v)-dup so
// the f32x2 multiplier is one LDS.64 broadcast. Two launches (b0 = 0, 32):
// W (64 MB) stays mostly L2-resident across the second launch.
// ---------------------------------------------------------------------------
__global__ void __launch_bounds__(128)
k_uhat(const float* __restrict__ x, const float* __restrict__ W, int b_base) {
    __shared__ float  Wsh[8192];
    __shared__ float2 xdup[BG][D_DIM];

    const int i = blockIdx.x;
    const int t = threadIdx.x;

    {
        const char* Wg = reinterpret_cast<const char*>(W + (size_t)i * 8192);
        U8* Ws8 = reinterpret_cast<U8*>(Wsh);
        #pragma unroll
        for (int r = 0; r < 8; r++)
            Ws8[t + 128 * r] = ldg_v8_stream(Wg + 32 * (t + 128 * r));
    }
    {
        #pragma unroll
        for (int r = 0; r < 4; r++) {
            const int e = t + 128 * r;
            const int lb = e >> 4, d = e & 15;
            const float v = x[((size_t)(b_base + lb) * I_CAPS + i) * D_DIM + d];
            xdup[lb][d] = make_float2(v, v);
        }
    }
    __syncthreads();

    const int j  = t >> 2;
    const int k0 = (t & 3) * 4;

    unsigned long long wA[D_DIM], wB[D_DIM];
    #pragma unroll
    for (int d = 0; d < D_DIM; d++) {
        const float* wp = &Wsh[j * 256 + d * 16 + k0];
        wA[d] = *reinterpret_cast<const unsigned long long*>(wp);
        wB[d] = *reinterpret_cast<const unsigned long long*>(wp + 2);
    }

    __half* outp = g_uhat + ((size_t)b_base * I_CAPS + (size_t)i) * JK + 4 * t;
    #pragma unroll 2
    for (int lb = 0; lb < BG; lb++) {
        unsigned long long u01 = 0ull, u23 = 0ull;
        #pragma unroll
        for (int d = 0; d < D_DIM; d++) {
            const unsigned long long xx =
                *reinterpret_cast<const unsigned long long*>(&xdup[lb][d]);
            fma2(u01, xx, wA[d]);
            fma2(u23, xx, wB[d]);
        }
        const float2 a = up2(u01), c = up2(u23);
        __half2 h0 = __float22half2_rn(make_float2(a.x, a.y));
        __half2 h1 = __float22half2_rn(make_float2(c.x, c.y));
        uint2 st;
        st.x = *reinterpret_cast<unsigned int*>(&h0);
        st.y = *reinterpret_cast<unsigned int*>(&h1);
        *reinterpret_cast<uint2*>(outp + (size_t)lb * ((size_t)I_CAPS * JK)) = st;
    }
}

// ---------------------------------------------------------------------------
// Routing pass, FULL batch (grid 32 x 64 = 2048 CTAs: the measured-fastest
// pass configuration, 4.67 TB/s). blockIdx.y = b, blockIdx.x = chunk of 64 i.
// 4 warps x 16 i. Lane l owns j=l, all k=16: ONE 32B LDG per i.
// MODE 1: lane-local logit dot; softmax over j = 5-shuffle z-allreduce
// (no max subtraction: |logit| <= ||u||*||o|| ~ 16, exp safe in fp32).
// ---------------------------------------------------------------------------
template <int MODE>
__global__ void __launch_bounds__(128, 8)
k_pass(int which_out) {
    __shared__ float red[4][16 * 33];

    const int b = blockIdx.y;
    const int t = threadIdx.x;
    const int w = t >> 5;
    const int l = t & 31;

    float o[16];
    if (MODE == 1) {
        const float* outv = (which_out == 0) ? g_out1 : g_outc;
        const float4* op = reinterpret_cast<const float4*>(
            outv + (size_t)b * JK + l * 16);
        #pragma unroll
        for (int q = 0; q < 4; q++) {
            float4 v = op[q];
            o[q * 4] = v.x; o[q * 4 + 1] = v.y; o[q * 4 + 2] = v.z; o[q * 4 + 3] = v.w;
        }
    }

    float acc[16];
    #pragma unroll
    for (int m = 0; m < 16; m++) acc[m] = 0.f;

    const __half* base = g_uhat + ((size_t)b * I_CAPS
                       + (size_t)(blockIdx.x * 64 + w * 16)) * JK;
    const char* p = reinterpret_cast<const char*>(base) + 32 * l;

    #pragma unroll
    for (int ii = 0; ii < 16; ii++) {
        const U8 r8 = ldg_v8(p + ii * 1024);

        float u[16];
        {
            const unsigned int* pa = &r8.a.x;
            const unsigned int* pb = &r8.b.x;
            #pragma unroll
            for (int h = 0; h < 4; h++) {
                float2 va = __half22float2(*reinterpret_cast<const __half2*>(&pa[h]));
                u[h * 2] = va.x; u[h * 2 + 1] = va.y;
                float2 vb = __half22float2(*reinterpret_cast<const __half2*>(&pb[h]));
                u[8 + h * 2] = vb.x; u[8 + h * 2 + 1] = vb.y;
            }
        }

        if (MODE == 1) {
            float lg = 0.f;
            #pragma unroll
            for (int m = 0; m < 16; m++) lg = fmaf(u[m], o[m], lg);
            const float e = __expf(lg);
            const float z = warp_sum(e);
            const float c = __fdividef(e, z);
            #pragma unroll
            for (int m = 0; m < 16; m++) acc[m] = fmaf(c, u[m], acc[m]);
        } else {
            #pragma unroll
            for (int m = 0; m < 16; m++) acc[m] += u[m];
        }
    }

    #pragma unroll
    for (int m = 0; m < 16; m++) red[w][m * 33 + l] = acc[m];
    __syncthreads();

    const int lo = t >> 2;
    const int mo = (t & 3) * 4;
    float4 s;
    float* sp = &s.x;
    #pragma unroll
    for (int c = 0; c < 4; c++) {
        float v = 0.f;
        #pragma unroll
        for (int w2 = 0; w2 < 4; w2++) v += red[w2][(mo + c) * 33 + lo];
        sp[c] = v;
    }
    *reinterpret_cast<float4*>(
        &g_part[((size_t)blockIdx.x * B_SZ + b) * JK + 4 * t]) = s;
}

// ---------------------------------------------------------------------------
// Squash (full batch): reduce 32 chunk-partials, squash per (b,j) over k=16.
// mode 0 -> g_out1 ; mode 1 -> g_outc = g_out1 + squash ; mode 2 -> d_out.
// ---------------------------------------------------------------------------
__global__ void __launch_bounds__(512)
k_squash(int mode, float* __restrict__ dout) {
    const int b = blockIdx.x;
    const int t = threadIdx.x;

    float v = 0.f;
    #pragma unroll
    for (int c = 0; c < NCHUNK; c++) v += g_part[((size_t)c * B_SZ + b) * JK + t];
    if (mode == 0) v *= (1.f / 32.f);

    float sq = v * v;
    sq += __shfl_xor_sync(0xffffffffu, sq, 1);
    sq += __shfl_xor_sync(0xffffffffu, sq, 2);
    sq += __shfl_xor_sync(0xffffffffu, sq, 4);
    sq += __shfl_xor_sync(0xffffffffu, sq, 8);

    const float scale = sq / ((1.f + sq) * sqrtf(sq + 1e-7f));
    const float o = scale * v;

    if (mode == 0)      g_out1[(size_t)b * JK + t] = o;
    else if (mode == 1) g_outc[(size_t)b * JK + t] = g_out1[(size_t)b * JK + t] + o;
    else                dout[(size_t)b * JK + t] = o;
}

// ---------------------------------------------------------------------------
extern "C" void kernel_launch(void* const* d_in, const int* in_sizes, int n_in,
                              void* d_out, int out_size) {
    const float* x = (const float*)d_in[0];
    const float* W = (const float*)d_in[1];
    if (n_in >= 2 && in_sizes[0] == 16777216 && in_sizes[1] == 2097152) {
        const float* tmp = x; x = W; W = tmp;
    }
    float* out = (float*)d_out;

    // k_uhat grouped (W L2-reuse across the two launches)
    k_uhat<<<I_CAPS, 128>>>(x, W, 0);
    k_uhat<<<I_CAPS, 128>>>(x, W, BG);

    // Routing rounds at full batch (measured-fastest pass configuration)
    dim3 pg(NCHUNK, B_SZ);
    k_pass<0><<<pg, 128>>>(0);           // round 1
    k_squash<<<B_SZ, 512>>>(0, nullptr);
    k_pass<1><<<pg, 128>>>(0);           // round 2
    k_squash<<<B_SZ, 512>>>(1, nullptr);
    k_pass<1><<<pg, 128>>>(1);           // round 3
    k_squash<<<B_SZ, 512>>>(2, out);
}